// round 1
// baseline (speedup 1.0000x reference)
#include <cuda_runtime.h>
#include <math.h>

// Problem constants
#define Bb 2048
#define Kk 100000
#define Dd 50
#define BM 64
#define BK 64
#define SPLITK 18
#define KLEN 5556  // ceil(100000/18)

// Split-K partial scratch (device globals; no allocation allowed)
__device__ float g_pu[(size_t)SPLITK * Bb * Dd];  // 7.37 MB
__device__ float g_pm[SPLITK * Bb];
__device__ float g_ps[SPLITK * Bb];

// Dynamic smem layout (floats)
#define SM_XT  0                      // xT[50][64]
#define SM_MCT (SM_XT + 50*BM)        // McT[50][64]
#define SM_MC  (SM_MCT + 50*BK)       // Mc[64][52] row-major (padded)
#define SM_PM  (SM_MC + BK*52)        // P[64][65]  (pad 65 -> conflict-free col reads)
#define SM_SC  (SM_PM + BM*65)        // scale[64]
#define SM_TOT (SM_SC + BM)           // total floats = 13952 -> 55808 bytes

__global__ __launch_bounds__(256, 2)
void attn_partial_kernel(const float* __restrict__ x, const float* __restrict__ M) {
    extern __shared__ float sm[];
    float* xT  = sm + SM_XT;
    float* mcT = sm + SM_MCT;
    float* mc  = sm + SM_MC;
    float* Pm  = sm + SM_PM;
    float* scs = sm + SM_SC;

    const int tid   = threadIdx.x;
    const int row0  = blockIdx.x * BM;
    const int split = blockIdx.y;
    const int kb    = split * KLEN;
    const int ke    = min(Kk, kb + KLEN);

    const int ty = tid >> 4;   // 0..15 : which 4-row group
    const int tx = tid & 15;   // 0..15 : which 4-col group (GEMM1) / 4-d group (GEMM2)

    // Load x tile -> xT[d][i] (coalesced global reads)
    for (int e = tid; e < BM * Dd; e += 256) {
        int i = e / Dd, d = e - i * Dd;
        xT[d * BM + i] = x[(size_t)(row0 + i) * Dd + d];
    }

    float m_run[4], s_run[4], u[4][4];
#pragma unroll
    for (int ii = 0; ii < 4; ii++) {
        m_run[ii] = -INFINITY;
        s_run[ii] = 0.f;
#pragma unroll
        for (int dd = 0; dd < 4; dd++) u[ii][dd] = 0.f;
    }

    __syncthreads();

    for (int cs = kb; cs < ke; cs += BK) {
        const int nv = min(BK, ke - cs);

        // ---- Load M chunk into both layouts (coalesced global) ----
        for (int e = tid; e < BK * Dd; e += 256) {
            int j = e / Dd, d = e - j * Dd;
            float v = (j < nv) ? M[(size_t)(cs + j) * Dd + d] : 0.f;
            mc[j * 52 + d]  = v;
            mcT[d * BK + j] = v;
        }
        __syncthreads();

        // ---- GEMM1: S[64][64] = xT' * McT' (4x4 register tile/thread) ----
        float acc[4][4];
#pragma unroll
        for (int ii = 0; ii < 4; ii++)
#pragma unroll
            for (int jj = 0; jj < 4; jj++) acc[ii][jj] = 0.f;

#pragma unroll 10
        for (int d = 0; d < Dd; d++) {
            float4 a4 = *reinterpret_cast<const float4*>(&xT[d * BM + 4 * ty]);
            float4 b4 = *reinterpret_cast<const float4*>(&mcT[d * BK + 4 * tx]);
            float av[4] = {a4.x, a4.y, a4.z, a4.w};
            float bv[4] = {b4.x, b4.y, b4.z, b4.w};
#pragma unroll
            for (int ii = 0; ii < 4; ii++)
#pragma unroll
                for (int jj = 0; jj < 4; jj++)
                    acc[ii][jj] = fmaf(av[ii], bv[jj], acc[ii][jj]);
        }

        // ---- Online softmax update (rows live in 16-lane groups) ----
#pragma unroll
        for (int ii = 0; ii < 4; ii++) {
            float rmax = fmaxf(fmaxf(acc[ii][0], acc[ii][1]),
                               fmaxf(acc[ii][2], acc[ii][3]));
#pragma unroll
            for (int mm = 1; mm < 16; mm <<= 1)
                rmax = fmaxf(rmax, __shfl_xor_sync(0xffffffffu, rmax, mm));

            float mnew = fmaxf(m_run[ii], rmax);
            float sc   = __expf(m_run[ii] - mnew);  // 0 on first chunk (-inf)

            float rs = 0.f;
#pragma unroll
            for (int jj = 0; jj < 4; jj++) {
                float pv = (4 * tx + jj < nv) ? __expf(acc[ii][jj] - mnew) : 0.f;
                rs += pv;
                Pm[(4 * ty + ii) * 65 + 4 * tx + jj] = pv;
            }
#pragma unroll
            for (int mm = 1; mm < 16; mm <<= 1)
                rs += __shfl_xor_sync(0xffffffffu, rs, mm);

            s_run[ii] = s_run[ii] * sc + rs;
            m_run[ii] = mnew;
            if (tx == 0) scs[4 * ty + ii] = sc;
        }
        __syncthreads();  // Pm, scs, (mc already) visible

        // ---- GEMM2: u[64][50] += P[64][64] @ Mc[64][50] ----
        // 16 ty-groups x 13 tx-groups of 4x4 (tx>=13 idle; d=4*tx+dd, masked at d>=50 on store)
        if (tx < 13) {
#pragma unroll
            for (int ii = 0; ii < 4; ii++) {
                float sc = scs[4 * ty + ii];
#pragma unroll
                for (int dd = 0; dd < 4; dd++) u[ii][dd] *= sc;
            }
#pragma unroll 8
            for (int j = 0; j < BK; j++) {
                float4 b4 = *reinterpret_cast<const float4*>(&mc[j * 52 + 4 * tx]);
                float bv[4] = {b4.x, b4.y, b4.z, b4.w};
#pragma unroll
                for (int ii = 0; ii < 4; ii++) {
                    float pv = Pm[(4 * ty + ii) * 65 + j];  // broadcast within lanes
#pragma unroll
                    for (int dd = 0; dd < 4; dd++)
                        u[ii][dd] = fmaf(pv, bv[dd], u[ii][dd]);
                }
            }
        }
        __syncthreads();  // protect mc/mcT/Pm before next chunk's loads
    }

    // ---- Write split-K partials ----
    if (tx < 13) {
#pragma unroll
        for (int ii = 0; ii < 4; ii++) {
            int r = row0 + 4 * ty + ii;
#pragma unroll
            for (int dd = 0; dd < 4; dd++) {
                int d = 4 * tx + dd;
                if (d < Dd)
                    g_pu[((size_t)split * Bb + r) * Dd + d] = u[ii][dd];
            }
        }
    }
    if (tx == 0) {
#pragma unroll
        for (int ii = 0; ii < 4; ii++) {
            int r = row0 + 4 * ty + ii;
            g_pm[split * Bb + r] = m_run[ii];
            g_ps[split * Bb + r] = s_run[ii];
        }
    }
}

__global__ void attn_combine_kernel(const float* __restrict__ x,
                                    float* __restrict__ out) {
    int b = blockIdx.x;
    int t = threadIdx.x;  // 64 threads

    float gm = -INFINITY;
#pragma unroll
    for (int p = 0; p < SPLITK; p++) gm = fmaxf(gm, g_pm[p * Bb + b]);

    float w[SPLITK];
    float denom = 0.f;
#pragma unroll
    for (int p = 0; p < SPLITK; p++) {
        w[p] = __expf(g_pm[p * Bb + b] - gm);
        denom += g_ps[p * Bb + b] * w[p];
    }

    if (t < Dd) {
        float acc = 0.f;
#pragma unroll
        for (int p = 0; p < SPLITK; p++)
            acc += g_pu[((size_t)p * Bb + b) * Dd + t] * w[p];
        out[(size_t)b * (2 * Dd) + Dd + t] = acc / denom;
        out[(size_t)b * (2 * Dd) + t]      = x[(size_t)b * Dd + t];
    }
}

extern "C" void kernel_launch(void* const* d_in, const int* in_sizes, int n_in,
                              void* d_out, int out_size) {
    const float* x = (const float*)d_in[0];
    const float* M = (const float*)d_in[1];
    // Defensive: disambiguate by element count in case of input-order surprises
    if (n_in >= 2 && in_sizes[0] == Kk * Dd && in_sizes[1] == Bb * Dd) {
        x = (const float*)d_in[1];
        M = (const float*)d_in[0];
    }
    float* out = (float*)d_out;

    cudaFuncSetAttribute(attn_partial_kernel,
                         cudaFuncAttributeMaxDynamicSharedMemorySize,
                         SM_TOT * (int)sizeof(float));

    attn_partial_kernel<<<dim3(Bb / BM, SPLITK), 256, SM_TOT * sizeof(float)>>>(x, M);
    attn_combine_kernel<<<Bb, 64>>>(x, d_out ? out : out);
}

// round 3
// speedup vs baseline: 3.6499x; 3.6499x over previous
#include <cuda_runtime.h>
#include <cuda_bf16.h>
#include <cstdint>
#include <math.h>

// ---------------- problem constants ----------------
#define Bb 2048
#define Kk 100000
#define Dd 50
#define BM 128
#define BN 128
#define SPLIT 9
#define KLEN ((Kk + SPLIT - 1) / SPLIT)   // 11112

// split-K partial scratch
__device__ float g_pu[(size_t)SPLIT * Bb * Dd];
__device__ float g_pden[SPLIT * Bb];

// smem layout (bytes): 4 tiles of 128 rows x 128B (64 bf16 dims), SW128
#define SM_XH 0
#define SM_XL 16384
#define SM_MH 32768
#define SM_ML 49152
#define SM_TOTAL 65536

#define SWZ(o) ((o) ^ (((o) >> 3) & 0x70))

__device__ __forceinline__ uint32_t smem_u32(const void* p) {
    uint32_t a;
    asm("{ .reg .u64 t; cvta.to.shared.u64 t, %1; cvt.u32.u64 %0, t; }" : "=r"(a) : "l"(p));
    return a;
}

__device__ __forceinline__ void ldsm4(uint32_t addr, uint32_t r[4]) {
    asm volatile("ldmatrix.sync.aligned.m8n8.x4.shared.b16 {%0,%1,%2,%3}, [%4];"
                 : "=r"(r[0]), "=r"(r[1]), "=r"(r[2]), "=r"(r[3]) : "r"(addr));
}
__device__ __forceinline__ void ldsm4t(uint32_t addr, uint32_t r[4]) {
    asm volatile("ldmatrix.sync.aligned.m8n8.x4.trans.shared.b16 {%0,%1,%2,%3}, [%4];"
                 : "=r"(r[0]), "=r"(r[1]), "=r"(r[2]), "=r"(r[3]) : "r"(addr));
}
__device__ __forceinline__ void mma16816(float c[4], const uint32_t a[4],
                                         uint32_t b0, uint32_t b1) {
    asm volatile("mma.sync.aligned.m16n8k16.row.col.f32.bf16.bf16.f32 "
                 "{%0,%1,%2,%3}, {%4,%5,%6,%7}, {%8,%9}, {%0,%1,%2,%3};"
                 : "+f"(c[0]), "+f"(c[1]), "+f"(c[2]), "+f"(c[3])
                 : "r"(a[0]), "r"(a[1]), "r"(a[2]), "r"(a[3]), "r"(b0), "r"(b1));
}

__device__ __forceinline__ void split_pack(float v0, float v1, uint32_t& hi, uint32_t& lo) {
    __nv_bfloat16 h0 = __float2bfloat16(v0), h1 = __float2bfloat16(v1);
    float l0f = v0 - __bfloat162float(h0), l1f = v1 - __bfloat162float(h1);
    __nv_bfloat16 l0 = __float2bfloat16(l0f), l1 = __float2bfloat16(l1f);
    hi = (uint32_t)__bfloat16_as_ushort(h0) | ((uint32_t)__bfloat16_as_ushort(h1) << 16);
    lo = (uint32_t)__bfloat16_as_ushort(l0) | ((uint32_t)__bfloat16_as_ushort(l1) << 16);
}

// =====================================================================
__global__ __launch_bounds__(256, 1)
void attn_mma_kernel(const float* __restrict__ x, const float* __restrict__ M) {
    extern __shared__ __align__(1024) char smem[];
    const uint32_t sb = smem_u32(smem);
    const int tid = threadIdx.x;
    const int wid = tid >> 5;
    const int lane = tid & 31;
    const int row0 = blockIdx.x * BM;
    const int split = blockIdx.y;
    const int kb = split * KLEN;
    const int ke = min(Kk, kb + KLEN);

    // zero all smem once (pads beyond dim 50 stay zero forever)
    for (int i = tid; i < SM_TOTAL / 4; i += 256)
        reinterpret_cast<uint32_t*>(smem)[i] = 0;
    __syncthreads();

    // x tile -> bf16 hi/lo, SW128 [row][dim]
    for (int e = tid; e < BM * Dd; e += 256) {
        int r = e / Dd, d = e - r * Dd;
        float v = x[(size_t)(row0 + r) * Dd + d];
        __nv_bfloat16 h = __float2bfloat16(v);
        __nv_bfloat16 l = __float2bfloat16(v - __bfloat162float(h));
        uint32_t off = (uint32_t)(r * 128 + d * 2), sw = SWZ(off);
        *reinterpret_cast<__nv_bfloat16*>(smem + SM_XH + sw) = h;
        *reinterpret_cast<__nv_bfloat16*>(smem + SM_XL + sw) = l;
    }
    __syncthreads();

    // resident x A-fragments (4 k-steps over padded D=64)
    uint32_t axh[4][4], axl[4][4];
    {
        int arow = wid * 16 + (lane & 15);
        int ahalf = (lane >> 4) & 1;
#pragma unroll
        for (int ks = 0; ks < 4; ks++) {
            uint32_t off = (uint32_t)(arow * 128 + ks * 32 + ahalf * 16);
            ldsm4(sb + SM_XH + SWZ(off), axh[ks]);
            ldsm4(sb + SM_XL + SWZ(off), axl[ks]);
        }
    }

    float u[8][4];
#pragma unroll
    for (int t = 0; t < 8; t++)
#pragma unroll
        for (int j = 0; j < 4; j++) u[t][j] = 0.f;
    float rs0 = 0.f, rs1 = 0.f;

    // prefetch chunk 0 into registers (25 floats/thread = 128*50/256)
    float pf[25];
    {
        int lim = min(BN, ke - kb) * Dd;
        const float* src = M + (size_t)kb * Dd;
#pragma unroll
        for (int i = 0; i < 25; i++) {
            int idx = tid + i * 256;
            pf[i] = (idx < lim) ? src[idx] : 0.f;
        }
    }

    const int brow = (lane & 7) + ((lane & 16) ? 8 : 0);   // GEMM1 B ldsm row
    const int bhalf = (lane >> 3) & 1;
    const int trow = (lane & 7) + ((lane & 8) ? 8 : 0);    // GEMM2 B ldsm.trans row
    const int thalf = (lane >> 4) & 1;

    for (int cs = kb; cs < ke; cs += BN) {
        const int nv = min(BN, ke - cs);

        __syncthreads();   // previous chunk's smem reads done
        // store prefetched chunk -> MH/ML (hi/lo split)
#pragma unroll
        for (int i = 0; i < 25; i++) {
            int idx = tid + i * 256;
            int s = idx / Dd, d = idx - s * Dd;
            float v = pf[i];
            __nv_bfloat16 h = __float2bfloat16(v);
            __nv_bfloat16 l = __float2bfloat16(v - __bfloat162float(h));
            uint32_t off = (uint32_t)(s * 128 + d * 2), sw = SWZ(off);
            *reinterpret_cast<__nv_bfloat16*>(smem + SM_MH + sw) = h;
            *reinterpret_cast<__nv_bfloat16*>(smem + SM_ML + sw) = l;
        }
        __syncthreads();

        // prefetch next chunk (LDGs overlap this chunk's compute)
        if (cs + BN < ke) {
            int lim = min(BN, ke - cs - BN) * Dd;
            const float* src = M + (size_t)(cs + BN) * Dd;
#pragma unroll
            for (int i = 0; i < 25; i++) {
                int idx = tid + i * 256;
                pf[i] = (idx < lim) ? src[idx] : 0.f;
            }
        }

        // ---- GEMM1: scores[16 x 128] per warp, 3-term bf16 split ----
        float c[16][4];
#pragma unroll
        for (int t = 0; t < 16; t++)
#pragma unroll
            for (int j = 0; j < 4; j++) c[t][j] = 0.f;

#pragma unroll
        for (int ks = 0; ks < 4; ks++) {
#pragma unroll
            for (int p = 0; p < 8; p++) {
                uint32_t off = (uint32_t)((16 * p + brow) * 128 + ks * 32 + bhalf * 16);
                uint32_t bh[4], bl[4];
                ldsm4(sb + SM_MH + SWZ(off), bh);
                ldsm4(sb + SM_ML + SWZ(off), bl);
                mma16816(c[2 * p],     axh[ks], bh[0], bh[1]);
                mma16816(c[2 * p],     axl[ks], bh[0], bh[1]);
                mma16816(c[2 * p],     axh[ks], bl[0], bl[1]);
                mma16816(c[2 * p + 1], axh[ks], bh[2], bh[3]);
                mma16816(c[2 * p + 1], axl[ks], bh[2], bh[3]);
                mma16816(c[2 * p + 1], axh[ks], bl[2], bl[3]);
            }
        }

        // ---- exp (masked) + rowsum ----
#pragma unroll
        for (int t = 0; t < 16; t++) {
            int col0 = 8 * t + 2 * (lane & 3);
            float p0 = (col0     < nv) ? __expf(c[t][0]) : 0.f;
            float p1 = (col0 + 1 < nv) ? __expf(c[t][1]) : 0.f;
            float p2 = (col0     < nv) ? __expf(c[t][2]) : 0.f;
            float p3 = (col0 + 1 < nv) ? __expf(c[t][3]) : 0.f;
            c[t][0] = p0; c[t][1] = p1; c[t][2] = p2; c[t][3] = p3;
            rs0 += p0 + p1;
            rs1 += p2 + p3;
        }

        // ---- GEMM2: u[16 x 64] += P · M, P A-frags straight from regs ----
#pragma unroll
        for (int s = 0; s < 8; s++) {
            uint32_t ph[4], pl[4];
            split_pack(c[2 * s][0],     c[2 * s][1],     ph[0], pl[0]);
            split_pack(c[2 * s][2],     c[2 * s][3],     ph[1], pl[1]);
            split_pack(c[2 * s + 1][0], c[2 * s + 1][1], ph[2], pl[2]);
            split_pack(c[2 * s + 1][2], c[2 * s + 1][3], ph[3], pl[3]);
#pragma unroll
            for (int ep = 0; ep < 4; ep++) {
                uint32_t off = (uint32_t)((16 * s + trow) * 128 + ep * 32 + thalf * 16);
                uint32_t bh[4], bl[4];
                ldsm4t(sb + SM_MH + SWZ(off), bh);
                ldsm4t(sb + SM_ML + SWZ(off), bl);
                mma16816(u[2 * ep],     ph, bh[0], bh[1]);
                mma16816(u[2 * ep],     pl, bh[0], bh[1]);
                mma16816(u[2 * ep],     ph, bl[0], bl[1]);
                mma16816(u[2 * ep + 1], ph, bh[2], bh[3]);
                mma16816(u[2 * ep + 1], pl, bh[2], bh[3]);
                mma16816(u[2 * ep + 1], ph, bl[2], bl[3]);
            }
        }
    }

    // ---- rowsum reduce across the 4 lanes sharing a row ----
    rs0 += __shfl_xor_sync(0xffffffffu, rs0, 1);
    rs0 += __shfl_xor_sync(0xffffffffu, rs0, 2);
    rs1 += __shfl_xor_sync(0xffffffffu, rs1, 1);
    rs1 += __shfl_xor_sync(0xffffffffu, rs1, 2);

    const int g = lane >> 2;
    const int r0 = row0 + wid * 16 + g;
    const int r1 = r0 + 8;

    if ((lane & 3) == 0) {
        g_pden[split * Bb + r0] = rs0;
        g_pden[split * Bb + r1] = rs1;
    }

    size_t base0 = ((size_t)split * Bb + r0) * Dd;
    size_t base1 = ((size_t)split * Bb + r1) * Dd;
#pragma unroll
    for (int t = 0; t < 8; t++) {
        int d0 = 8 * t + 2 * (lane & 3);
        if (d0 < Dd) {
            g_pu[base0 + d0] = u[t][0];
            g_pu[base1 + d0] = u[t][2];
            if (d0 + 1 < Dd) {
                g_pu[base0 + d0 + 1] = u[t][1];
                g_pu[base1 + d0 + 1] = u[t][3];
            }
        }
    }
}

// =====================================================================
__global__ void attn_combine_kernel(const float* __restrict__ x, float* __restrict__ out) {
    int b = blockIdx.x;
    int t = threadIdx.x;   // 64 threads
    if (t < Dd) {
        float den = 0.f, acc = 0.f;
#pragma unroll
        for (int s = 0; s < SPLIT; s++) {
            den += g_pden[s * Bb + b];
            acc += g_pu[((size_t)s * Bb + b) * Dd + t];
        }
        out[(size_t)b * (2 * Dd) + Dd + t] = acc / den;
        out[(size_t)b * (2 * Dd) + t] = x[(size_t)b * Dd + t];
    }
}

extern "C" void kernel_launch(void* const* d_in, const int* in_sizes, int n_in,
                              void* d_out, int out_size) {
    const float* x = (const float*)d_in[0];
    const float* M = (const float*)d_in[1];
    if (n_in >= 2 && in_sizes[0] == Kk * Dd && in_sizes[1] == Bb * Dd) {
        x = (const float*)d_in[1];
        M = (const float*)d_in[0];
    }
    float* out = (float*)d_out;

    cudaFuncSetAttribute(attn_mma_kernel,
                         cudaFuncAttributeMaxDynamicSharedMemorySize, SM_TOTAL);

    attn_mma_kernel<<<dim3(Bb / BM, SPLIT), 256, SM_TOTAL>>>(x, M);
    attn_combine_kernel<<<Bb, 64>>>(x, out);
}

// round 4
// speedup vs baseline: 4.2737x; 1.1709x over previous
#include <cuda_runtime.h>
#include <cuda_bf16.h>
#include <cstdint>
#include <math.h>

// ---------------- problem constants ----------------
#define Bb 2048
#define Kk 100000
#define Dd 50
#define BM 128
#define BN 128
#define SPLIT 9
#define KLEN (88 * 128)                 // 11264, multiple of BN
#define NCHUNKS ((Kk + BN - 1) / BN)    // 782

// split-K partial scratch
__device__ float g_pu[(size_t)SPLIT * Bb * Dd];
__device__ float g_pden[SPLIT * Bb];
// pre-split, pre-swizzled M images: per chunk 32 KB = [hi 16K | lo 16K]
__device__ __align__(16) unsigned char g_img[(size_t)NCHUNKS * 32768];

// smem layout (bytes)
#define SM_XH 0
#define SM_XL 16384
#define SM_B0 32768
#define SM_B1 65536
#define SM_TOTAL 98304

#define SWZ(o) ((o) ^ (((o) >> 3) & 0x70))

__device__ __forceinline__ uint32_t smem_u32(const void* p) {
    uint32_t a;
    asm("{ .reg .u64 t; cvta.to.shared.u64 t, %1; cvt.u32.u64 %0, t; }" : "=r"(a) : "l"(p));
    return a;
}
__device__ __forceinline__ void ldsm4(uint32_t addr, uint32_t r[4]) {
    asm volatile("ldmatrix.sync.aligned.m8n8.x4.shared.b16 {%0,%1,%2,%3}, [%4];"
                 : "=r"(r[0]), "=r"(r[1]), "=r"(r[2]), "=r"(r[3]) : "r"(addr));
}
__device__ __forceinline__ void ldsm4t(uint32_t addr, uint32_t r[4]) {
    asm volatile("ldmatrix.sync.aligned.m8n8.x4.trans.shared.b16 {%0,%1,%2,%3}, [%4];"
                 : "=r"(r[0]), "=r"(r[1]), "=r"(r[2]), "=r"(r[3]) : "r"(addr));
}
__device__ __forceinline__ void mma16816(float c[4], const uint32_t a[4],
                                         uint32_t b0, uint32_t b1) {
    asm volatile("mma.sync.aligned.m16n8k16.row.col.f32.bf16.bf16.f32 "
                 "{%0,%1,%2,%3}, {%4,%5,%6,%7}, {%8,%9}, {%0,%1,%2,%3};"
                 : "+f"(c[0]), "+f"(c[1]), "+f"(c[2]), "+f"(c[3])
                 : "r"(a[0]), "r"(a[1]), "r"(a[2]), "r"(a[3]), "r"(b0), "r"(b1));
}
__device__ __forceinline__ void split_pack(float v0, float v1, uint32_t& hi, uint32_t& lo) {
    __nv_bfloat16 h0 = __float2bfloat16(v0), h1 = __float2bfloat16(v1);
    float l0f = v0 - __bfloat162float(h0), l1f = v1 - __bfloat162float(h1);
    __nv_bfloat16 l0 = __float2bfloat16(l0f), l1 = __float2bfloat16(l1f);
    hi = (uint32_t)__bfloat16_as_ushort(h0) | ((uint32_t)__bfloat16_as_ushort(h1) << 16);
    lo = (uint32_t)__bfloat16_as_ushort(l0) | ((uint32_t)__bfloat16_as_ushort(l1) << 16);
}
__device__ __forceinline__ void copy_chunk_async(uint32_t dst, const unsigned char* src, int tid) {
#pragma unroll
    for (int j = 0; j < 8; j++) {
        uint32_t off = (uint32_t)tid * 16 + j * 4096;
        asm volatile("cp.async.cg.shared.global [%0], [%1], 16;"
                     :: "r"(dst + off), "l"(src + off) : "memory");
    }
}

// ============ prep: M -> bf16 hi/lo pre-swizzled chunk images ============
__global__ void prep_kernel(const float* __restrict__ M) {
    int chunk = blockIdx.x;
    size_t base = (size_t)chunk * 32768;
    for (int e = threadIdx.x; e < 128 * 64; e += 256) {
        int s = e >> 6, d = e & 63;
        int slot = chunk * 128 + s;
        float v = (slot < Kk && d < Dd) ? M[(size_t)slot * Dd + d] : 0.f;
        __nv_bfloat16 h = __float2bfloat16(v);
        __nv_bfloat16 l = __float2bfloat16(v - __bfloat162float(h));
        uint32_t sw = SWZ((uint32_t)(s * 128 + d * 2));
        *reinterpret_cast<__nv_bfloat16*>(g_img + base + sw) = h;
        *reinterpret_cast<__nv_bfloat16*>(g_img + base + 16384 + sw) = l;
    }
}

// =====================================================================
__global__ __launch_bounds__(256, 1)
void attn_mma_kernel(const float* __restrict__ x) {
    extern __shared__ __align__(1024) char smem[];
    const uint32_t sb = smem_u32(smem);
    const int tid = threadIdx.x;
    const int wid = tid >> 5;
    const int lane = tid & 31;
    const int row0 = blockIdx.x * BM;
    const int split = blockIdx.y;
    const int kb = split * KLEN;
    const int ke = min(Kk, kb + KLEN);
    const int nch = (ke - kb + BN - 1) / BN;
    const int chunk0 = kb / BN;

    // zero x tiles (pads beyond dim 50 stay zero)
    for (int i = tid; i < 32768 / 4; i += 256)
        reinterpret_cast<uint32_t*>(smem)[i] = 0;
    __syncthreads();

    // x tile -> bf16 hi/lo, SW128 [row][dim]
    for (int e = tid; e < BM * Dd; e += 256) {
        int r = e / Dd, d = e - r * Dd;
        float v = x[(size_t)(row0 + r) * Dd + d];
        __nv_bfloat16 h = __float2bfloat16(v);
        __nv_bfloat16 l = __float2bfloat16(v - __bfloat162float(h));
        uint32_t off = (uint32_t)(r * 128 + d * 2), sw = SWZ(off);
        *reinterpret_cast<__nv_bfloat16*>(smem + SM_XH + sw) = h;
        *reinterpret_cast<__nv_bfloat16*>(smem + SM_XL + sw) = l;
    }

    // issue chunk 0 copy while x conversion settles
    copy_chunk_async(sb + SM_B0, g_img + (size_t)chunk0 * 32768, tid);
    asm volatile("cp.async.commit_group;" ::: "memory");
    __syncthreads();

    // resident x A-fragments (4 k-steps over padded D=64)
    uint32_t axh[4][4], axl[4][4];
    {
        int arow = wid * 16 + (lane & 15);
        int ahalf = (lane >> 4) & 1;
#pragma unroll
        for (int ks = 0; ks < 4; ks++) {
            uint32_t off = (uint32_t)(arow * 128 + ks * 32 + ahalf * 16);
            ldsm4(sb + SM_XH + SWZ(off), axh[ks]);
            ldsm4(sb + SM_XL + SWZ(off), axl[ks]);
        }
    }

    float u[8][4];
#pragma unroll
    for (int t = 0; t < 8; t++)
#pragma unroll
        for (int j = 0; j < 4; j++) u[t][j] = 0.f;
    float rs0 = 0.f, rs1 = 0.f;

    const int brow = (lane & 7) + ((lane & 16) ? 8 : 0);   // GEMM1 B ldsm row
    const int bhalf = (lane >> 3) & 1;
    const int trow = (lane & 7) + ((lane & 8) ? 8 : 0);    // GEMM2 B ldsm.trans row
    const int thalf = (lane >> 4) & 1;

    for (int i = 0; i < nch; i++) {
        const uint32_t mh = sb + ((i & 1) ? SM_B1 : SM_B0);
        const uint32_t ml = mh + 16384;
        const int nv = min(BN, ke - (kb + i * BN));

        // issue next chunk into the other buffer (safe: its readers synced last iter)
        if (i + 1 < nch)
            copy_chunk_async(sb + ((i & 1) ? SM_B0 : SM_B1),
                             g_img + (size_t)(chunk0 + i + 1) * 32768, tid);
        asm volatile("cp.async.commit_group;" ::: "memory");
        asm volatile("cp.async.wait_group 1;" ::: "memory");
        __syncthreads();

        // ---- GEMM1: scores[16 x 128] per warp, 3-term bf16 split ----
        float c[16][4];
#pragma unroll
        for (int t = 0; t < 16; t++)
#pragma unroll
            for (int j = 0; j < 4; j++) c[t][j] = 0.f;

#pragma unroll
        for (int ks = 0; ks < 4; ks++) {
#pragma unroll
            for (int p = 0; p < 8; p++) {
                uint32_t off = (uint32_t)((16 * p + brow) * 128 + ks * 32 + bhalf * 16);
                uint32_t bh[4], bl[4];
                ldsm4(mh + SWZ(off), bh);
                ldsm4(ml + SWZ(off), bl);
                mma16816(c[2 * p],     axh[ks], bh[0], bh[1]);
                mma16816(c[2 * p],     axl[ks], bh[0], bh[1]);
                mma16816(c[2 * p],     axh[ks], bl[0], bl[1]);
                mma16816(c[2 * p + 1], axh[ks], bh[2], bh[3]);
                mma16816(c[2 * p + 1], axl[ks], bh[2], bh[3]);
                mma16816(c[2 * p + 1], axh[ks], bl[2], bl[3]);
            }
        }

        // ---- GEMM2 with fused exp/pack per s-tile ----
#pragma unroll
        for (int s = 0; s < 8; s++) {
            // exp (masked) + rowsum for tiles t=2s, 2s+1
            float pv[2][4];
#pragma unroll
            for (int h = 0; h < 2; h++) {
                int t = 2 * s + h;
                int col0 = 8 * t + 2 * (lane & 3);
                pv[h][0] = (col0     < nv) ? __expf(c[t][0]) : 0.f;
                pv[h][1] = (col0 + 1 < nv) ? __expf(c[t][1]) : 0.f;
                pv[h][2] = (col0     < nv) ? __expf(c[t][2]) : 0.f;
                pv[h][3] = (col0 + 1 < nv) ? __expf(c[t][3]) : 0.f;
                rs0 += pv[h][0] + pv[h][1];
                rs1 += pv[h][2] + pv[h][3];
            }
            uint32_t ph[4], pl[4];
            split_pack(pv[0][0], pv[0][1], ph[0], pl[0]);
            split_pack(pv[0][2], pv[0][3], ph[1], pl[1]);
            split_pack(pv[1][0], pv[1][1], ph[2], pl[2]);
            split_pack(pv[1][2], pv[1][3], ph[3], pl[3]);

#pragma unroll
            for (int ep = 0; ep < 4; ep++) {
                uint32_t off = (uint32_t)((16 * s + trow) * 128 + ep * 32 + thalf * 16);
                uint32_t bh[4], bl[4];
                ldsm4t(mh + SWZ(off), bh);
                ldsm4t(ml + SWZ(off), bl);
                mma16816(u[2 * ep],     ph, bh[0], bh[1]);
                mma16816(u[2 * ep],     pl, bh[0], bh[1]);
                mma16816(u[2 * ep],     ph, bl[0], bl[1]);
                if (ep < 3) {  // cols 56..63 are all-zero pad: skip
                    mma16816(u[2 * ep + 1], ph, bh[2], bh[3]);
                    mma16816(u[2 * ep + 1], pl, bh[2], bh[3]);
                    mma16816(u[2 * ep + 1], ph, bl[2], bl[3]);
                }
            }
        }
        __syncthreads();   // all reads of this buffer done before it is refilled
    }

    // ---- rowsum reduce across the 4 lanes sharing a row ----
    rs0 += __shfl_xor_sync(0xffffffffu, rs0, 1);
    rs0 += __shfl_xor_sync(0xffffffffu, rs0, 2);
    rs1 += __shfl_xor_sync(0xffffffffu, rs1, 1);
    rs1 += __shfl_xor_sync(0xffffffffu, rs1, 2);

    const int g = lane >> 2;
    const int r0 = row0 + wid * 16 + g;
    const int r1 = r0 + 8;

    if ((lane & 3) == 0) {
        g_pden[split * Bb + r0] = rs0;
        g_pden[split * Bb + r1] = rs1;
    }

    size_t base0 = ((size_t)split * Bb + r0) * Dd;
    size_t base1 = ((size_t)split * Bb + r1) * Dd;
#pragma unroll
    for (int t = 0; t < 7; t++) {
        int d0 = 8 * t + 2 * (lane & 3);
        if (d0 < Dd) {
            g_pu[base0 + d0] = u[t][0];
            g_pu[base1 + d0] = u[t][2];
            if (d0 + 1 < Dd) {
                g_pu[base0 + d0 + 1] = u[t][1];
                g_pu[base1 + d0 + 1] = u[t][3];
            }
        }
    }
}

// =====================================================================
__global__ void attn_combine_kernel(const float* __restrict__ x, float* __restrict__ out) {
    int b = blockIdx.x;
    int t = threadIdx.x;   // 64 threads
    if (t < Dd) {
        float den = 0.f, acc = 0.f;
#pragma unroll
        for (int s = 0; s < SPLIT; s++) {
            den += g_pden[s * Bb + b];
            acc += g_pu[((size_t)s * Bb + b) * Dd + t];
        }
        out[(size_t)b * (2 * Dd) + Dd + t] = acc / den;
        out[(size_t)b * (2 * Dd) + t] = x[(size_t)b * Dd + t];
    }
}

extern "C" void kernel_launch(void* const* d_in, const int* in_sizes, int n_in,
                              void* d_out, int out_size) {
    const float* x = (const float*)d_in[0];
    const float* M = (const float*)d_in[1];
    if (n_in >= 2 && in_sizes[0] == Kk * Dd && in_sizes[1] == Bb * Dd) {
        x = (const float*)d_in[1];
        M = (const float*)d_in[0];
    }
    float* out = (float*)d_out;

    cudaFuncSetAttribute(attn_mma_kernel,
                         cudaFuncAttributeMaxDynamicSharedMemorySize, SM_TOTAL);

    prep_kernel<<<NCHUNKS, 256>>>(M);
    attn_mma_kernel<<<dim3(Bb / BM, SPLIT), 256, SM_TOTAL>>>(x);
    attn_combine_kernel<<<Bb, 64>>>(x, out);
}

// round 5
// speedup vs baseline: 4.2760x; 1.0005x over previous
#include <cuda_runtime.h>
#include <cuda_bf16.h>
#include <cstdint>
#include <math.h>

// ---------------- problem constants ----------------
#define Bb 2048
#define Kk 100000
#define Dd 50
#define BM 128
#define BN 128
#define SPLIT 9
#define CPS 88                           // chunks per split (last split: 78)
#define NCHUNKS ((Kk + BN - 1) / BN)     // 782

// split-K partial scratch
__device__ float g_pu[(size_t)SPLIT * Bb * Dd];
__device__ float g_pden[SPLIT * Bb];
// pre-split, pre-swizzled M images: per chunk 32 KB = [hi 16K | lo 16K]
__device__ __align__(16) unsigned char g_img[(size_t)NCHUNKS * 32768];

// smem layout (bytes)
#define SM_XH 0
#define SM_XL 16384
#define SM_B0 32768
#define SM_B1 65536
#define SM_TOTAL 98304

#define SWZ(o) ((o) ^ (((o) >> 3) & 0x70))

__device__ __forceinline__ uint32_t smem_u32(const void* p) {
    uint32_t a;
    asm("{ .reg .u64 t; cvta.to.shared.u64 t, %1; cvt.u32.u64 %0, t; }" : "=r"(a) : "l"(p));
    return a;
}
__device__ __forceinline__ void ldsm4(uint32_t addr, uint32_t r[4]) {
    asm volatile("ldmatrix.sync.aligned.m8n8.x4.shared.b16 {%0,%1,%2,%3}, [%4];"
                 : "=r"(r[0]), "=r"(r[1]), "=r"(r[2]), "=r"(r[3]) : "r"(addr));
}
__device__ __forceinline__ void ldsm4t(uint32_t addr, uint32_t r[4]) {
    asm volatile("ldmatrix.sync.aligned.m8n8.x4.trans.shared.b16 {%0,%1,%2,%3}, [%4];"
                 : "=r"(r[0]), "=r"(r[1]), "=r"(r[2]), "=r"(r[3]) : "r"(addr));
}
__device__ __forceinline__ void mma16816(float c[4], const uint32_t a[4],
                                         uint32_t b0, uint32_t b1) {
    asm volatile("mma.sync.aligned.m16n8k16.row.col.f32.bf16.bf16.f32 "
                 "{%0,%1,%2,%3}, {%4,%5,%6,%7}, {%8,%9}, {%0,%1,%2,%3};"
                 : "+f"(c[0]), "+f"(c[1]), "+f"(c[2]), "+f"(c[3])
                 : "r"(a[0]), "r"(a[1]), "r"(a[2]), "r"(a[3]), "r"(b0), "r"(b1));
}
__device__ __forceinline__ void split_pack(float v0, float v1, uint32_t& hi, uint32_t& lo) {
    __nv_bfloat16 h0 = __float2bfloat16(v0), h1 = __float2bfloat16(v1);
    float l0f = v0 - __bfloat162float(h0), l1f = v1 - __bfloat162float(h1);
    __nv_bfloat16 l0 = __float2bfloat16(l0f), l1 = __float2bfloat16(l1f);
    hi = (uint32_t)__bfloat16_as_ushort(h0) | ((uint32_t)__bfloat16_as_ushort(h1) << 16);
    lo = (uint32_t)__bfloat16_as_ushort(l0) | ((uint32_t)__bfloat16_as_ushort(l1) << 16);
}
__device__ __forceinline__ void copy_chunk_async512(uint32_t dst, const unsigned char* src, int tid) {
#pragma unroll
    for (int j = 0; j < 4; j++) {
        uint32_t off = (uint32_t)tid * 16 + j * 8192;
        asm volatile("cp.async.cg.shared.global [%0], [%1], 16;"
                     :: "r"(dst + off), "l"(src + off) : "memory");
    }
}

// ============ prep: M -> bf16 hi/lo pre-swizzled chunk images ============
// Within a row s, SWZ key is constant: SWZ(s*128 + 2d) = s*128 + (2d ^ ((s&7)<<4)).
// Thread handles 8 consecutive dims -> one 16B hi store + one 16B lo store.
__global__ void prep_kernel(const float* __restrict__ M) {
    int chunk = blockIdx.x;
    size_t base = (size_t)chunk * 32768;
    for (int e = threadIdx.x; e < 128 * 8; e += 256) {
        int s = e >> 3, dg = e & 7;         // row s, dim group dg (dims 8dg..8dg+7)
        int slot = chunk * 128 + s;
        uint32_t key = (uint32_t)((s & 7) << 4);
        ushort hi[8], lo[8];
#pragma unroll
        for (int q = 0; q < 8; q++) {
            int d = 8 * dg + q;
            float v = (slot < Kk && d < Dd) ? M[(size_t)slot * Dd + d] : 0.f;
            __nv_bfloat16 h = __float2bfloat16(v);
            __nv_bfloat16 l = __float2bfloat16(v - __bfloat162float(h));
            hi[q] = __bfloat16_as_ushort(h);
            lo[q] = __bfloat16_as_ushort(l);
        }
        uint32_t off = (uint32_t)(s * 128) + (((uint32_t)(16 * dg)) ^ key);
        *reinterpret_cast<uint4*>(g_img + base + off) = *reinterpret_cast<uint4*>(hi);
        *reinterpret_cast<uint4*>(g_img + base + 16384 + off) = *reinterpret_cast<uint4*>(lo);
    }
}

// =====================================================================
__global__ __launch_bounds__(512, 1)
void attn_mma_kernel(const float* __restrict__ x) {
    extern __shared__ __align__(1024) char smem[];
    const uint32_t sb = smem_u32(smem);
    const int tid = threadIdx.x;
    const int wid = tid >> 5;
    const int lane = tid & 31;
    const int wr = wid >> 1;        // row group (16 rows)
    const int wc = wid & 1;         // chunk half (64 slots)
    const int row0 = blockIdx.x * BM;
    const int split = blockIdx.y;
    const int chunk0 = split * CPS;
    const int nch = min(CPS, NCHUNKS - chunk0);
    const int kb = chunk0 * BN;
    const int ke = min(Kk, kb + nch * BN);

    // zero x tiles (pads beyond dim 50 stay zero)
    for (int i = tid; i < 32768 / 4; i += 512)
        reinterpret_cast<uint32_t*>(smem)[i] = 0;
    __syncthreads();

    // x tile -> bf16 hi/lo, SW128 [row][dim]
    for (int e = tid; e < BM * Dd; e += 512) {
        int r = e / Dd, d = e - r * Dd;
        float v = x[(size_t)(row0 + r) * Dd + d];
        __nv_bfloat16 h = __float2bfloat16(v);
        __nv_bfloat16 l = __float2bfloat16(v - __bfloat162float(h));
        uint32_t off = (uint32_t)(r * 128 + d * 2), sw = SWZ(off);
        *reinterpret_cast<__nv_bfloat16*>(smem + SM_XH + sw) = h;
        *reinterpret_cast<__nv_bfloat16*>(smem + SM_XL + sw) = l;
    }

    copy_chunk_async512(sb + SM_B0, g_img + (size_t)chunk0 * 32768, tid);
    asm volatile("cp.async.commit_group;" ::: "memory");
    __syncthreads();

    // resident x A-fragments for this warp's 16 rows
    uint32_t axh[4][4], axl[4][4];
    {
        int arow = wr * 16 + (lane & 15);
        int ahalf = (lane >> 4) & 1;
#pragma unroll
        for (int ks = 0; ks < 4; ks++) {
            uint32_t off = (uint32_t)(arow * 128 + ks * 32 + ahalf * 16);
            ldsm4(sb + SM_XH + SWZ(off), axh[ks]);
            ldsm4(sb + SM_XL + SWZ(off), axl[ks]);
        }
    }

    float u[8][4];
#pragma unroll
    for (int t = 0; t < 8; t++)
#pragma unroll
        for (int j = 0; j < 4; j++) u[t][j] = 0.f;
    float rs0 = 0.f, rs1 = 0.f;

    const int brow = (lane & 7) + ((lane & 16) ? 8 : 0);   // GEMM1 B ldsm row
    const int bhalf = (lane >> 3) & 1;
    const int trow = (lane & 7) + ((lane & 8) ? 8 : 0);    // GEMM2 B ldsm.trans row
    const int thalf = (lane >> 4) & 1;

    for (int i = 0; i < nch; i++) {
        const uint32_t mh = sb + ((i & 1) ? SM_B1 : SM_B0);
        const uint32_t ml = mh + 16384;
        const int nv = min(BN, ke - (kb + i * BN));

        if (i + 1 < nch)
            copy_chunk_async512(sb + ((i & 1) ? SM_B0 : SM_B1),
                                g_img + (size_t)(chunk0 + i + 1) * 32768, tid);
        asm volatile("cp.async.commit_group;" ::: "memory");
        asm volatile("cp.async.wait_group 1;" ::: "memory");
        __syncthreads();

        // ---- fused per-16-slot tile: GEMM1 -> exp -> pack -> GEMM2 ----
#pragma unroll
        for (int s = 0; s < 4; s++) {
            const int st = 4 * wc + s;      // 16-slot tile index in chunk

            // GEMM1 partial: c2[2][4] = scores rows(16) x slots(16)
            float c2[2][4];
#pragma unroll
            for (int h = 0; h < 2; h++)
#pragma unroll
                for (int j = 0; j < 4; j++) c2[h][j] = 0.f;
#pragma unroll
            for (int ks = 0; ks < 4; ks++) {
                uint32_t off = (uint32_t)((16 * st + brow) * 128 + ks * 32 + bhalf * 16);
                uint32_t bh[4], bl[4];
                ldsm4(mh + SWZ(off), bh);
                ldsm4(ml + SWZ(off), bl);
                mma16816(c2[0], axh[ks], bh[0], bh[1]);
                mma16816(c2[0], axl[ks], bh[0], bh[1]);
                mma16816(c2[0], axh[ks], bl[0], bl[1]);
                mma16816(c2[1], axh[ks], bh[2], bh[3]);
                mma16816(c2[1], axl[ks], bh[2], bh[3]);
                mma16816(c2[1], axh[ks], bl[2], bl[3]);
            }

            // exp (masked) + rowsum
            const int cb = 16 * st + 2 * (lane & 3);
            float p00 = (cb     < nv) ? __expf(c2[0][0]) : 0.f;
            float p01 = (cb + 1 < nv) ? __expf(c2[0][1]) : 0.f;
            float p02 = (cb     < nv) ? __expf(c2[0][2]) : 0.f;
            float p03 = (cb + 1 < nv) ? __expf(c2[0][3]) : 0.f;
            float p10 = (cb + 8 < nv) ? __expf(c2[1][0]) : 0.f;
            float p11 = (cb + 9 < nv) ? __expf(c2[1][1]) : 0.f;
            float p12 = (cb + 8 < nv) ? __expf(c2[1][2]) : 0.f;
            float p13 = (cb + 9 < nv) ? __expf(c2[1][3]) : 0.f;
            rs0 += p00 + p01 + p10 + p11;
            rs1 += p02 + p03 + p12 + p13;

            uint32_t ph[4], pl[4];
            split_pack(p00, p01, ph[0], pl[0]);
            split_pack(p02, p03, ph[1], pl[1]);
            split_pack(p10, p11, ph[2], pl[2]);
            split_pack(p12, p13, ph[3], pl[3]);

            // GEMM2: u += P(16x16 slots) * M(16 slots x 64 dims)
#pragma unroll
            for (int ep = 0; ep < 4; ep++) {
                uint32_t off = (uint32_t)((16 * st + trow) * 128 + ep * 32 + thalf * 16);
                uint32_t bh[4], bl[4];
                ldsm4t(mh + SWZ(off), bh);
                ldsm4t(ml + SWZ(off), bl);
                mma16816(u[2 * ep],     ph, bh[0], bh[1]);
                mma16816(u[2 * ep],     pl, bh[0], bh[1]);
                mma16816(u[2 * ep],     ph, bl[0], bl[1]);
                if (ep < 3) {   // dims 56..63 are zero pad
                    mma16816(u[2 * ep + 1], ph, bh[2], bh[3]);
                    mma16816(u[2 * ep + 1], pl, bh[2], bh[3]);
                    mma16816(u[2 * ep + 1], ph, bl[2], bl[3]);
                }
            }
        }
        __syncthreads();   // reads done before buffer refill next iter
    }

    // ---- rowsum reduce across the 4 lanes sharing a row ----
    rs0 += __shfl_xor_sync(0xffffffffu, rs0, 1);
    rs0 += __shfl_xor_sync(0xffffffffu, rs0, 2);
    rs1 += __shfl_xor_sync(0xffffffffu, rs1, 1);
    rs1 += __shfl_xor_sync(0xffffffffu, rs1, 2);

    // ---- cross-wc reduction through smem (x tiles now dead) ----
    __syncthreads();
    float* red = reinterpret_cast<float*>(smem);          // [128][64] u partials
    float* redrs = red + 128 * 64;                        // [128] rowsums
    const int g = lane >> 2;

    if (wc == 1) {
#pragma unroll
        for (int t = 0; t < 7; t++) {
            int d0 = 8 * t + 2 * (lane & 3);
            red[(wr * 16 + g) * 64 + d0]     = u[t][0];
            red[(wr * 16 + g) * 64 + d0 + 1] = u[t][1];
            red[(wr * 16 + g + 8) * 64 + d0]     = u[t][2];
            red[(wr * 16 + g + 8) * 64 + d0 + 1] = u[t][3];
        }
        if ((lane & 3) == 0) {
            redrs[wr * 16 + g] = rs0;
            redrs[wr * 16 + g + 8] = rs1;
        }
    }
    __syncthreads();

    if (wc == 0) {
        const int r0 = row0 + wr * 16 + g;
        const int r1 = r0 + 8;
        rs0 += redrs[wr * 16 + g];
        rs1 += redrs[wr * 16 + g + 8];
        if ((lane & 3) == 0) {
            g_pden[split * Bb + r0] = rs0;
            g_pden[split * Bb + r1] = rs1;
        }
        size_t base0 = ((size_t)split * Bb + r0) * Dd;
        size_t base1 = ((size_t)split * Bb + r1) * Dd;
#pragma unroll
        for (int t = 0; t < 7; t++) {
            int d0 = 8 * t + 2 * (lane & 3);
            if (d0 < Dd) {
                g_pu[base0 + d0] = u[t][0] + red[(wr * 16 + g) * 64 + d0];
                g_pu[base1 + d0] = u[t][2] + red[(wr * 16 + g + 8) * 64 + d0];
                if (d0 + 1 < Dd) {
                    g_pu[base0 + d0 + 1] = u[t][1] + red[(wr * 16 + g) * 64 + d0 + 1];
                    g_pu[base1 + d0 + 1] = u[t][3] + red[(wr * 16 + g + 8) * 64 + d0 + 1];
                }
            }
        }
    }
}

// =====================================================================
__global__ void attn_combine_kernel(const float* __restrict__ x, float* __restrict__ out) {
    int b = blockIdx.x;
    int t = threadIdx.x;   // 64 threads
    if (t < Dd) {
        float den = 0.f, acc = 0.f;
#pragma unroll
        for (int s = 0; s < SPLIT; s++) {
            den += g_pden[s * Bb + b];
            acc += g_pu[((size_t)s * Bb + b) * Dd + t];
        }
        out[(size_t)b * (2 * Dd) + Dd + t] = acc / den;
        out[(size_t)b * (2 * Dd) + t] = x[(size_t)b * Dd + t];
    }
}

extern "C" void kernel_launch(void* const* d_in, const int* in_sizes, int n_in,
                              void* d_out, int out_size) {
    const float* x = (const float*)d_in[0];
    const float* M = (const float*)d_in[1];
    if (n_in >= 2 && in_sizes[0] == Kk * Dd && in_sizes[1] == Bb * Dd) {
        x = (const float*)d_in[1];
        M = (const float*)d_in[0];
    }
    float* out = (float*)d_out;

    cudaFuncSetAttribute(attn_mma_kernel,
                         cudaFuncAttributeMaxDynamicSharedMemorySize, SM_TOTAL);

    prep_kernel<<<NCHUNKS, 256>>>(M);
    attn_mma_kernel<<<dim3(Bb / BM, SPLIT), 512, SM_TOTAL>>>(x);
    attn_combine_kernel<<<Bb, 64>>>(x, out);
}